// round 2
// baseline (speedup 1.0000x reference)
#include <cuda_runtime.h>

// ---------------------------------------------------------------------------
// TPoseHuman fused 6-part MLP ensemble, fp32 with packed f32x2 FMA (sm_103a).
//
// Per (n,p):  x9 = [tpts(3), bigpts(3), viewdir(3)]   (frame rows of W1 folded
//             into an effective bias b1eff)
//   h1 = relu(x9 @ W1r + b1eff)         (9 -> 256)
//   h2 = relu(h1 @ W2 + b2)             (256 -> 256)   <- dominant GEMM
//   raw/occ = h2 @ [W3|Wocc] + [b3|bocc](256 -> 21), occ -> sigmoid
//   masked by tflag, mean over p.
// Output (N, 27) = [raw_mean(20), occ_mean(1), tocc(6)]
//
// One CTA = 64 points, loops over the 6 parts, fully fused (H1/H2 in SMEM,
// W2 streamed via double-buffered 16x256 tiles). No atomics, no extra passes.
//
// R1 fix: tflag is serialized as int32 (jax bool -> int32), not uint8.
// ---------------------------------------------------------------------------

#define NPTS      65536
#define PPARTS    6
#define DDIM      256
#define IN9       9
#define RTOT      21      // 20 raw + 1 occ
#define RPAD      24
#define OUTC      27
#define TM        64      // points per CTA
#define NTHREADS  256

#define PITCH_H1  68      // 64 + pad (4-way write conflicts in layer1, ok)
#define PITCH_H2  260     // 256 + 4
#define PITCH_W3  260

// packed f32x2 FMA: d = a*b + d  (elementwise on 2 packed fp32)
#define FMA2(accv, av, bv) \
    asm("fma.rn.f32x2 %0, %1, %2, %0;" : "+l"(accv) : "l"(av), "l"(bv))

__device__ __forceinline__ unsigned long long pack2(float x) {
    union { unsigned long long u; float2 f; } c;
    c.f = make_float2(x, x);
    return c.u;
}
__device__ __forceinline__ float2 unpack2(unsigned long long v) {
    union { unsigned long long u; float2 f; } c;
    c.u = v;
    return c.f;
}

// ------------------------- persistent scratch ------------------------------
__device__ float g_b1eff[PPARTS * DDIM];          // folded frame bias
__device__ float g_W1r  [PPARTS * IN9 * DDIM];    // 9 live rows of W1
__device__ float g_W3cT [PPARTS * RTOT * DDIM];   // [p][r][d] transposed W3|Wocc
__device__ float g_b3c  [PPARTS * RTOT];

// ------------------------- precompute kernel -------------------------------
__global__ void precompute_kernel(const float* __restrict__ W1,
                                  const float* __restrict__ b1,
                                  const float* __restrict__ W3,
                                  const float* __restrict__ b3,
                                  const float* __restrict__ Wocc,
                                  const float* __restrict__ bocc,
                                  const float* __restrict__ frame) {
    int p = blockIdx.x;
    int d = threadIdx.x;
    const int rows[IN9] = {0, 1, 2, 11, 12, 13, 14, 15, 16};

    float be = b1[p * DDIM + d];
#pragma unroll
    for (int f = 0; f < 8; ++f)
        be += frame[f] * W1[(p * 17 + 3 + f) * DDIM + d];
    g_b1eff[p * DDIM + d] = be;

#pragma unroll
    for (int i = 0; i < IN9; ++i)
        g_W1r[(p * IN9 + i) * DDIM + d] = W1[(p * 17 + rows[i]) * DDIM + d];

    for (int r = 0; r < 20; ++r)
        g_W3cT[(p * RTOT + r) * DDIM + d] = W3[(p * DDIM + d) * 20 + r];
    g_W3cT[(p * RTOT + 20) * DDIM + d] = Wocc[p * DDIM + d];

    if (d < 20)  g_b3c[p * RTOT + d]  = b3[p * 20 + d];
    if (d == 20) g_b3c[p * RTOT + 20] = bocc[p];
}

// ------------------------- main fused kernel -------------------------------
__global__ void __launch_bounds__(NTHREADS, 1)
fused_kernel(const float* __restrict__ tpts,
             const float* __restrict__ bigpts,
             const float* __restrict__ viewdir,
             const float* __restrict__ W2,
             const float* __restrict__ b2g,
             const int* __restrict__ tflag,
             float* __restrict__ out) {
    extern __shared__ float sm[];
    float* sH1   = sm;                           // 256*68  = 17408
    float* sH2   = sH1  + DDIM * PITCH_H1;       // 64*260  = 16640
    float* sB    = sH2  + TM * PITCH_H2;         // 2*16*256=  8192
    float* sX    = sB   + 2 * 16 * DDIM;         // 64*12   =   768
    float* sW3   = sX   + TM * 12;               // 24*260  =  6240
    float* sb2   = sW3  + RPAD * PITCH_W3;       // 256
    float* sb3   = sb2  + DDIM;                  // 32
    float* sflag = sb3  + 32;                    // 384

    const int tid = threadIdx.x;
    const int tx  = tid & 31;
    const int ty  = tid >> 5;
    const int m0  = ty * 8;
    const int n0  = blockIdx.x * TM;

    // layer-3 / output mapping
    const int mm = tid >> 2;      // 0..63
    const int rg = tid & 3;       // r in [rg*6, rg*6+5]
    const int rbase = rg * 6;

    float accP[6] = {0.f, 0.f, 0.f, 0.f, 0.f, 0.f};

    // flags for all parts of this tile (int32-serialized bool; !=0 test is
    // also correct if the harness serialized bools as float32 bit patterns)
    for (int idx = tid; idx < TM * PPARTS; idx += NTHREADS)
        sflag[idx] = (tflag[n0 * PPARTS + idx] != 0) ? 1.f : 0.f;

    for (int p = 0; p < PPARTS; ++p) {
        // ---- phase A: stage per-part inputs / weights into SMEM ----
        for (int idx = tid; idx < TM * IN9; idx += NTHREADS) {
            int m = idx / IN9, i = idx % IN9;
            int gi = (n0 + m) * PPARTS + p;
            float v;
            if (i < 3)      v = tpts   [gi * 3 + i];
            else if (i < 6) v = bigpts [gi * 3 + (i - 3)];
            else            v = viewdir[gi * 3 + (i - 6)];
            sX[m * 12 + i] = v;
        }
        for (int idx = tid; idx < RPAD * DDIM; idx += NTHREADS) {
            int r = idx >> 8, d = idx & 255;
            sW3[r * PITCH_W3 + d] =
                (r < RTOT) ? g_W3cT[(p * RTOT + r) * DDIM + d] : 0.f;
        }
        sb2[tid] = b2g[p * DDIM + tid];
        if (tid < RPAD) sb3[tid] = (tid < RTOT) ? g_b3c[p * RTOT + tid] : 0.f;
        __syncthreads();

        // ---- layer 1: thread tid owns output column k = tid ----
        {
            float w[IN9];
#pragma unroll
            for (int i = 0; i < IN9; ++i)
                w[i] = g_W1r[(p * IN9 + i) * DDIM + tid];
            float be = g_b1eff[p * DDIM + tid];
            float* dst = sH1 + tid * PITCH_H1;
#pragma unroll 4
            for (int m4 = 0; m4 < TM; m4 += 4) {
                float res[4];
#pragma unroll
                for (int j = 0; j < 4; ++j) {
                    const float* xr = sX + (m4 + j) * 12;
                    float4 xa = *(const float4*)(xr);
                    float4 xb = *(const float4*)(xr + 4);
                    float  xs = xr[8];
                    float s = be;
                    s += xa.x * w[0]; s += xa.y * w[1]; s += xa.z * w[2];
                    s += xa.w * w[3]; s += xb.x * w[4]; s += xb.y * w[5];
                    s += xb.z * w[6]; s += xb.w * w[7]; s += xs   * w[8];
                    res[j] = fmaxf(s, 0.f);
                }
                *(float4*)(dst + m4) = make_float4(res[0], res[1], res[2], res[3]);
            }
        }
        __syncthreads();

        // ---- layer 2: (64 x 256) = (64 x 256) @ (256 x 256), f32x2 FMA ----
        unsigned long long acc[8][4];
#pragma unroll
        for (int i = 0; i < 8; ++i)
#pragma unroll
            for (int q = 0; q < 4; ++q) acc[i][q] = 0ull;

        const float4* W2g = (const float4*)(W2 + (size_t)p * DDIM * DDIM);
        float4* sB4 = (float4*)sB;
        float4 reg[4];
#pragma unroll
        for (int j = 0; j < 4; ++j) reg[j] = W2g[j * 256 + tid];
#pragma unroll
        for (int j = 0; j < 4; ++j) sB4[j * 256 + tid] = reg[j];
        __syncthreads();

#pragma unroll 1
        for (int kb = 0; kb < 16; ++kb) {
            const int cur = kb & 1;
            if (kb < 15) {
#pragma unroll
                for (int j = 0; j < 4; ++j)
                    reg[j] = W2g[(kb + 1) * 1024 + j * 256 + tid];
            }
            const float* Bb = sB + cur * 4096;
#pragma unroll
            for (int k = 0; k < 16; ++k) {
                const float* arow = sH1 + (kb * 16 + k) * PITCH_H1 + m0;
                float4 a0 = *(const float4*)(arow);
                float4 a1 = *(const float4*)(arow + 4);
                unsigned long long pa[8];
                pa[0] = pack2(a0.x); pa[1] = pack2(a0.y);
                pa[2] = pack2(a0.z); pa[3] = pack2(a0.w);
                pa[4] = pack2(a1.x); pa[5] = pack2(a1.y);
                pa[6] = pack2(a1.z); pa[7] = pack2(a1.w);
                ulonglong2 bA = *(const ulonglong2*)(Bb + k * 256 + tx * 4);
                ulonglong2 bB = *(const ulonglong2*)(Bb + k * 256 + 128 + tx * 4);
#pragma unroll
                for (int mI = 0; mI < 8; ++mI) {
                    FMA2(acc[mI][0], pa[mI], bA.x);
                    FMA2(acc[mI][1], pa[mI], bA.y);
                    FMA2(acc[mI][2], pa[mI], bB.x);
                    FMA2(acc[mI][3], pa[mI], bB.y);
                }
            }
            if (kb < 15) {
                const int nxt = cur ^ 1;
#pragma unroll
                for (int j = 0; j < 4; ++j)
                    sB4[nxt * 1024 + j * 256 + tid] = reg[j];
            }
            __syncthreads();
        }

        // epilogue: + b2, relu, store H2 (row-major, conflict-free f4 stores)
        {
            float4 b2a = *(const float4*)(sb2 + tx * 4);
            float4 b2b = *(const float4*)(sb2 + 128 + tx * 4);
#pragma unroll
            for (int mI = 0; mI < 8; ++mI) {
                float2 v0 = unpack2(acc[mI][0]);
                float2 v1 = unpack2(acc[mI][1]);
                float2 v2 = unpack2(acc[mI][2]);
                float2 v3 = unpack2(acc[mI][3]);
                float4 o0 = make_float4(fmaxf(v0.x + b2a.x, 0.f),
                                        fmaxf(v0.y + b2a.y, 0.f),
                                        fmaxf(v1.x + b2a.z, 0.f),
                                        fmaxf(v1.y + b2a.w, 0.f));
                float4 o1 = make_float4(fmaxf(v2.x + b2b.x, 0.f),
                                        fmaxf(v2.y + b2b.y, 0.f),
                                        fmaxf(v3.x + b2b.z, 0.f),
                                        fmaxf(v3.y + b2b.w, 0.f));
                float* hrow = sH2 + (m0 + mI) * PITCH_H2;
                *(float4*)(hrow + tx * 4)       = o0;
                *(float4*)(hrow + 128 + tx * 4) = o1;
            }
        }
        __syncthreads();

        // ---- layer 3: (64 x 21) = H2 @ W3c, thread = (mm, rg) ----
        {
            const float* hrow  = sH2 + mm * PITCH_H2;
            const float* wbase = sW3 + rbase * PITCH_W3;
            unsigned long long a6[6] = {0ull, 0ull, 0ull, 0ull, 0ull, 0ull};
#pragma unroll 4
            for (int d = 0; d < DDIM; d += 4) {
                ulonglong2 h2 = *(const ulonglong2*)(hrow + d);
#pragma unroll
                for (int j = 0; j < 6; ++j) {
                    ulonglong2 wv = *(const ulonglong2*)(wbase + j * PITCH_W3 + d);
                    FMA2(a6[j], h2.x, wv.x);
                    FMA2(a6[j], h2.y, wv.y);
                }
            }
            float flagv = sflag[mm * PPARTS + p];
#pragma unroll
            for (int j = 0; j < 6; ++j) {
                float2 c = unpack2(a6[j]);
                float v = c.x + c.y + sb3[rbase + j];
                if (rbase + j == 20) {
                    v = 1.f / (1.f + __expf(-v));
                    v *= flagv;
                    out[(size_t)(n0 + mm) * OUTC + 21 + p] = v;  // tocc
                } else {
                    v *= flagv;
                }
                accP[j] += v;
            }
        }
        __syncthreads();   // protect sX/sW3/sH1/sH2 before next part
    }

    // ---- final: masked means over 6 parts ----
    const float inv6 = 1.f / 6.f;
#pragma unroll
    for (int j = 0; j < 6; ++j) {
        int r = rbase + j;
        if (r < RTOT)
            out[(size_t)(n0 + mm) * OUTC + r] = accP[j] * inv6;
    }
}

// ------------------------- launch ------------------------------------------
extern "C" void kernel_launch(void* const* d_in, const int* in_sizes, int n_in,
                              void* d_out, int out_size) {
    const float* tpts    = (const float*)d_in[0];
    const float* bigpts  = (const float*)d_in[1];
    const float* viewdir = (const float*)d_in[2];
    // d_in[3] = dists, d_in[4] = part_dist : unused by reference
    const float* frame   = (const float*)d_in[5];
    const float* W1      = (const float*)d_in[6];
    const float* b1      = (const float*)d_in[7];
    const float* W2      = (const float*)d_in[8];
    const float* b2      = (const float*)d_in[9];
    const float* W3      = (const float*)d_in[10];
    const float* b3      = (const float*)d_in[11];
    const float* Wocc    = (const float*)d_in[12];
    const float* bocc    = (const float*)d_in[13];
    const int*   tflag   = (const int*)d_in[14];
    float* out = (float*)d_out;

    precompute_kernel<<<PPARTS, DDIM>>>(W1, b1, W3, b3, Wocc, bocc, frame);

    const size_t smemBytes =
        (size_t)(DDIM * PITCH_H1 + TM * PITCH_H2 + 2 * 16 * DDIM +
                 TM * 12 + RPAD * PITCH_W3 + DDIM + 32 + TM * PPARTS) *
        sizeof(float);
    cudaFuncSetAttribute(fused_kernel,
                         cudaFuncAttributeMaxDynamicSharedMemorySize,
                         (int)smemBytes);
    fused_kernel<<<NPTS / TM, NTHREADS, smemBytes>>>(tpts, bigpts, viewdir,
                                                     W2, b2, tflag, out);
}

// round 3
// speedup vs baseline: 1.0002x; 1.0002x over previous
#include <cuda_runtime.h>

// ---------------------------------------------------------------------------
// TPoseHuman fused 6-part MLP ensemble, fp32 with packed f32x2 FMA (sm_103a).
//
// Per (n,p):  x9 = [tpts(3), bigpts(3), viewdir(3)]   (frame rows of W1 folded
//             into an effective bias b1eff)
//   h1 = relu(x9 @ W1r + b1eff)         (9 -> 256)
//   h2 = relu(h1 @ W2 + b2)             (256 -> 256)   <- dominant GEMM
//   raw/occ = h2 @ [W3|Wocc] + [b3|bocc](256 -> 21), occ -> sigmoid
//   masked by tflag, mean over p.
// Output (N, 27) = [raw_mean(20), occ_mean(1), tocc(6)]
//
// One CTA = 64 points, loops over the 6 parts, fully fused (H1/H2 in SMEM,
// W2 streamed via double-buffered 16x256 tiles). No atomics, no extra passes.
//
// R1 fix: tflag is serialized as int32 (jax bool -> int32), not uint8.
// ---------------------------------------------------------------------------

#define NPTS      65536
#define PPARTS    6
#define DDIM      256
#define IN9       9
#define RTOT      21      // 20 raw + 1 occ
#define RPAD      24
#define OUTC      27
#define TM        64      // points per CTA
#define NTHREADS  256

#define PITCH_H1  68      // 64 + pad (4-way write conflicts in layer1, ok)
#define PITCH_H2  260     // 256 + 4
#define PITCH_W3  260

// packed f32x2 FMA: d = a*b + d  (elementwise on 2 packed fp32)
#define FMA2(accv, av, bv) \
    asm("fma.rn.f32x2 %0, %1, %2, %0;" : "+l"(accv) : "l"(av), "l"(bv))

__device__ __forceinline__ unsigned long long pack2(float x) {
    union { unsigned long long u; float2 f; } c;
    c.f = make_float2(x, x);
    return c.u;
}
__device__ __forceinline__ float2 unpack2(unsigned long long v) {
    union { unsigned long long u; float2 f; } c;
    c.u = v;
    return c.f;
}

// ------------------------- persistent scratch ------------------------------
__device__ float g_b1eff[PPARTS * DDIM];          // folded frame bias
__device__ float g_W1r  [PPARTS * IN9 * DDIM];    // 9 live rows of W1
__device__ float g_W3cT [PPARTS * RTOT * DDIM];   // [p][r][d] transposed W3|Wocc
__device__ float g_b3c  [PPARTS * RTOT];

// ------------------------- precompute kernel -------------------------------
__global__ void precompute_kernel(const float* __restrict__ W1,
                                  const float* __restrict__ b1,
                                  const float* __restrict__ W3,
                                  const float* __restrict__ b3,
                                  const float* __restrict__ Wocc,
                                  const float* __restrict__ bocc,
                                  const float* __restrict__ frame) {
    int p = blockIdx.x;
    int d = threadIdx.x;
    const int rows[IN9] = {0, 1, 2, 11, 12, 13, 14, 15, 16};

    float be = b1[p * DDIM + d];
#pragma unroll
    for (int f = 0; f < 8; ++f)
        be += frame[f] * W1[(p * 17 + 3 + f) * DDIM + d];
    g_b1eff[p * DDIM + d] = be;

#pragma unroll
    for (int i = 0; i < IN9; ++i)
        g_W1r[(p * IN9 + i) * DDIM + d] = W1[(p * 17 + rows[i]) * DDIM + d];

    for (int r = 0; r < 20; ++r)
        g_W3cT[(p * RTOT + r) * DDIM + d] = W3[(p * DDIM + d) * 20 + r];
    g_W3cT[(p * RTOT + 20) * DDIM + d] = Wocc[p * DDIM + d];

    if (d < 20)  g_b3c[p * RTOT + d]  = b3[p * 20 + d];
    if (d == 20) g_b3c[p * RTOT + 20] = bocc[p];
}

// ------------------------- main fused kernel -------------------------------
__global__ void __launch_bounds__(NTHREADS, 1)
fused_kernel(const float* __restrict__ tpts,
             const float* __restrict__ bigpts,
             const float* __restrict__ viewdir,
             const float* __restrict__ W2,
             const float* __restrict__ b2g,
             const int* __restrict__ tflag,
             float* __restrict__ out) {
    extern __shared__ float sm[];
    float* sH1   = sm;                           // 256*68  = 17408
    float* sH2   = sH1  + DDIM * PITCH_H1;       // 64*260  = 16640
    float* sB    = sH2  + TM * PITCH_H2;         // 2*16*256=  8192
    float* sX    = sB   + 2 * 16 * DDIM;         // 64*12   =   768
    float* sW3   = sX   + TM * 12;               // 24*260  =  6240
    float* sb2   = sW3  + RPAD * PITCH_W3;       // 256
    float* sb3   = sb2  + DDIM;                  // 32
    float* sflag = sb3  + 32;                    // 384

    const int tid = threadIdx.x;
    const int tx  = tid & 31;
    const int ty  = tid >> 5;
    const int m0  = ty * 8;
    const int n0  = blockIdx.x * TM;

    // layer-3 / output mapping
    const int mm = tid >> 2;      // 0..63
    const int rg = tid & 3;       // r in [rg*6, rg*6+5]
    const int rbase = rg * 6;

    float accP[6] = {0.f, 0.f, 0.f, 0.f, 0.f, 0.f};

    // flags for all parts of this tile (int32-serialized bool; !=0 test is
    // also correct if the harness serialized bools as float32 bit patterns)
    for (int idx = tid; idx < TM * PPARTS; idx += NTHREADS)
        sflag[idx] = (tflag[n0 * PPARTS + idx] != 0) ? 1.f : 0.f;

    for (int p = 0; p < PPARTS; ++p) {
        // ---- phase A: stage per-part inputs / weights into SMEM ----
        for (int idx = tid; idx < TM * IN9; idx += NTHREADS) {
            int m = idx / IN9, i = idx % IN9;
            int gi = (n0 + m) * PPARTS + p;
            float v;
            if (i < 3)      v = tpts   [gi * 3 + i];
            else if (i < 6) v = bigpts [gi * 3 + (i - 3)];
            else            v = viewdir[gi * 3 + (i - 6)];
            sX[m * 12 + i] = v;
        }
        for (int idx = tid; idx < RPAD * DDIM; idx += NTHREADS) {
            int r = idx >> 8, d = idx & 255;
            sW3[r * PITCH_W3 + d] =
                (r < RTOT) ? g_W3cT[(p * RTOT + r) * DDIM + d] : 0.f;
        }
        sb2[tid] = b2g[p * DDIM + tid];
        if (tid < RPAD) sb3[tid] = (tid < RTOT) ? g_b3c[p * RTOT + tid] : 0.f;
        __syncthreads();

        // ---- layer 1: thread tid owns output column k = tid ----
        {
            float w[IN9];
#pragma unroll
            for (int i = 0; i < IN9; ++i)
                w[i] = g_W1r[(p * IN9 + i) * DDIM + tid];
            float be = g_b1eff[p * DDIM + tid];
            float* dst = sH1 + tid * PITCH_H1;
#pragma unroll 4
            for (int m4 = 0; m4 < TM; m4 += 4) {
                float res[4];
#pragma unroll
                for (int j = 0; j < 4; ++j) {
                    const float* xr = sX + (m4 + j) * 12;
                    float4 xa = *(const float4*)(xr);
                    float4 xb = *(const float4*)(xr + 4);
                    float  xs = xr[8];
                    float s = be;
                    s += xa.x * w[0]; s += xa.y * w[1]; s += xa.z * w[2];
                    s += xa.w * w[3]; s += xb.x * w[4]; s += xb.y * w[5];
                    s += xb.z * w[6]; s += xb.w * w[7]; s += xs   * w[8];
                    res[j] = fmaxf(s, 0.f);
                }
                *(float4*)(dst + m4) = make_float4(res[0], res[1], res[2], res[3]);
            }
        }
        __syncthreads();

        // ---- layer 2: (64 x 256) = (64 x 256) @ (256 x 256), f32x2 FMA ----
        unsigned long long acc[8][4];
#pragma unroll
        for (int i = 0; i < 8; ++i)
#pragma unroll
            for (int q = 0; q < 4; ++q) acc[i][q] = 0ull;

        const float4* W2g = (const float4*)(W2 + (size_t)p * DDIM * DDIM);
        float4* sB4 = (float4*)sB;
        float4 reg[4];
#pragma unroll
        for (int j = 0; j < 4; ++j) reg[j] = W2g[j * 256 + tid];
#pragma unroll
        for (int j = 0; j < 4; ++j) sB4[j * 256 + tid] = reg[j];
        __syncthreads();

#pragma unroll 1
        for (int kb = 0; kb < 16; ++kb) {
            const int cur = kb & 1;
            if (kb < 15) {
#pragma unroll
                for (int j = 0; j < 4; ++j)
                    reg[j] = W2g[(kb + 1) * 1024 + j * 256 + tid];
            }
            const float* Bb = sB + cur * 4096;
#pragma unroll
            for (int k = 0; k < 16; ++k) {
                const float* arow = sH1 + (kb * 16 + k) * PITCH_H1 + m0;
                float4 a0 = *(const float4*)(arow);
                float4 a1 = *(const float4*)(arow + 4);
                unsigned long long pa[8];
                pa[0] = pack2(a0.x); pa[1] = pack2(a0.y);
                pa[2] = pack2(a0.z); pa[3] = pack2(a0.w);
                pa[4] = pack2(a1.x); pa[5] = pack2(a1.y);
                pa[6] = pack2(a1.z); pa[7] = pack2(a1.w);
                ulonglong2 bA = *(const ulonglong2*)(Bb + k * 256 + tx * 4);
                ulonglong2 bB = *(const ulonglong2*)(Bb + k * 256 + 128 + tx * 4);
#pragma unroll
                for (int mI = 0; mI < 8; ++mI) {
                    FMA2(acc[mI][0], pa[mI], bA.x);
                    FMA2(acc[mI][1], pa[mI], bA.y);
                    FMA2(acc[mI][2], pa[mI], bB.x);
                    FMA2(acc[mI][3], pa[mI], bB.y);
                }
            }
            if (kb < 15) {
                const int nxt = cur ^ 1;
#pragma unroll
                for (int j = 0; j < 4; ++j)
                    sB4[nxt * 1024 + j * 256 + tid] = reg[j];
            }
            __syncthreads();
        }

        // epilogue: + b2, relu, store H2 (row-major, conflict-free f4 stores)
        {
            float4 b2a = *(const float4*)(sb2 + tx * 4);
            float4 b2b = *(const float4*)(sb2 + 128 + tx * 4);
#pragma unroll
            for (int mI = 0; mI < 8; ++mI) {
                float2 v0 = unpack2(acc[mI][0]);
                float2 v1 = unpack2(acc[mI][1]);
                float2 v2 = unpack2(acc[mI][2]);
                float2 v3 = unpack2(acc[mI][3]);
                float4 o0 = make_float4(fmaxf(v0.x + b2a.x, 0.f),
                                        fmaxf(v0.y + b2a.y, 0.f),
                                        fmaxf(v1.x + b2a.z, 0.f),
                                        fmaxf(v1.y + b2a.w, 0.f));
                float4 o1 = make_float4(fmaxf(v2.x + b2b.x, 0.f),
                                        fmaxf(v2.y + b2b.y, 0.f),
                                        fmaxf(v3.x + b2b.z, 0.f),
                                        fmaxf(v3.y + b2b.w, 0.f));
                float* hrow = sH2 + (m0 + mI) * PITCH_H2;
                *(float4*)(hrow + tx * 4)       = o0;
                *(float4*)(hrow + 128 + tx * 4) = o1;
            }
        }
        __syncthreads();

        // ---- layer 3: (64 x 21) = H2 @ W3c, thread = (mm, rg) ----
        {
            const float* hrow  = sH2 + mm * PITCH_H2;
            const float* wbase = sW3 + rbase * PITCH_W3;
            unsigned long long a6[6] = {0ull, 0ull, 0ull, 0ull, 0ull, 0ull};
#pragma unroll 4
            for (int d = 0; d < DDIM; d += 4) {
                ulonglong2 h2 = *(const ulonglong2*)(hrow + d);
#pragma unroll
                for (int j = 0; j < 6; ++j) {
                    ulonglong2 wv = *(const ulonglong2*)(wbase + j * PITCH_W3 + d);
                    FMA2(a6[j], h2.x, wv.x);
                    FMA2(a6[j], h2.y, wv.y);
                }
            }
            float flagv = sflag[mm * PPARTS + p];
#pragma unroll
            for (int j = 0; j < 6; ++j) {
                float2 c = unpack2(a6[j]);
                float v = c.x + c.y + sb3[rbase + j];
                if (rbase + j == 20) {
                    v = 1.f / (1.f + __expf(-v));
                    v *= flagv;
                    out[(size_t)(n0 + mm) * OUTC + 21 + p] = v;  // tocc
                } else {
                    v *= flagv;
                }
                accP[j] += v;
            }
        }
        __syncthreads();   // protect sX/sW3/sH1/sH2 before next part
    }

    // ---- final: masked means over 6 parts ----
    const float inv6 = 1.f / 6.f;
#pragma unroll
    for (int j = 0; j < 6; ++j) {
        int r = rbase + j;
        if (r < RTOT)
            out[(size_t)(n0 + mm) * OUTC + r] = accP[j] * inv6;
    }
}

// ------------------------- launch ------------------------------------------
extern "C" void kernel_launch(void* const* d_in, const int* in_sizes, int n_in,
                              void* d_out, int out_size) {
    const float* tpts    = (const float*)d_in[0];
    const float* bigpts  = (const float*)d_in[1];
    const float* viewdir = (const float*)d_in[2];
    // d_in[3] = dists, d_in[4] = part_dist : unused by reference
    const float* frame   = (const float*)d_in[5];
    const float* W1      = (const float*)d_in[6];
    const float* b1      = (const float*)d_in[7];
    const float* W2      = (const float*)d_in[8];
    const float* b2      = (const float*)d_in[9];
    const float* W3      = (const float*)d_in[10];
    const float* b3      = (const float*)d_in[11];
    const float* Wocc    = (const float*)d_in[12];
    const float* bocc    = (const float*)d_in[13];
    const int*   tflag   = (const int*)d_in[14];
    float* out = (float*)d_out;

    precompute_kernel<<<PPARTS, DDIM>>>(W1, b1, W3, b3, Wocc, bocc, frame);

    const size_t smemBytes =
        (size_t)(DDIM * PITCH_H1 + TM * PITCH_H2 + 2 * 16 * DDIM +
                 TM * 12 + RPAD * PITCH_W3 + DDIM + 32 + TM * PPARTS) *
        sizeof(float);
    cudaFuncSetAttribute(fused_kernel,
                         cudaFuncAttributeMaxDynamicSharedMemorySize,
                         (int)smemBytes);
    fused_kernel<<<NPTS / TM, NTHREADS, smemBytes>>>(tpts, bigpts, viewdir,
                                                     W2, b2, tflag, out);
}

// round 6
// speedup vs baseline: 1.5089x; 1.5085x over previous
#include <cuda_runtime.h>
#include <cuda_bf16.h>

// ---------------------------------------------------------------------------
// TPoseHuman fused 6-part MLP — layer2 on mma.sync bf16 (3-pass hi/lo split).
// Baseline-PTX tensor path (mma.sync + ldmatrix + cp.async): compiles on the
// harness's family-level compute_103 target (tcgen05.ld is sm_103a-only).
//   layer1: scalar fp32 -> bf16 hi/lo A planes in smem (swizzled for ldmatrix)
//   layer2: D(64x256 f32, regs) += A(hi/lo) x B(W2^T hi/lo); B streamed from
//           pre-swizzled global images via cp.async 2-slot ring (8 stages/part)
//   layer3: scalar FFMA2 from smem h2 (proven R3 path)
// ---------------------------------------------------------------------------

#define NPTS    65536
#define PPARTS  6
#define TM      64
#define NCTAS   (NPTS / TM)       // 1024
#define THREADS 256
#define RTOT    21
#define OUTC    27
#define NSTAGES (PPARTS * 8)      // 48 global B stages

// ---- smem byte offsets ----
#define OFF_B    0u        // 2 x 32768 cp.async ring
#define OFF_A    65536u    // A_hi 32768 | A_lo 32768 | 1024 pad (h2 aliases)
#define OFF_H2   65536u    // 64 rows x 260 floats = 66560 bytes
#define OFF_W3   132096u   // 24 x 260 floats = 24960
#define OFF_B2   157056u   // 256 floats
#define OFF_B3   158080u   // 24 floats (pad 32)
#define OFF_FLAG 158208u   // 64 floats
#define OFF_W1R  158464u   // 9*256 floats
#define OFF_B1E  167680u   // 256 floats
#define SMEM_BYTES 168704

// ---------------------------------------------------------------------------
// asm helpers (all baseline PTX, sm_80-era)
// ---------------------------------------------------------------------------
__device__ __forceinline__ unsigned smem_to_u32(const void* p) {
    unsigned a;
    asm("{ .reg .u64 t; cvta.to.shared.u64 t, %1; cvt.u32.u64 %0, t; }"
        : "=r"(a) : "l"(p));
    return a;
}
#define LDSM4(r, addr) \
    asm volatile("ldmatrix.sync.aligned.m8n8.x4.shared.b16 {%0,%1,%2,%3}, [%4];" \
        : "=r"((r)[0]), "=r"((r)[1]), "=r"((r)[2]), "=r"((r)[3]) : "r"(addr))
#define MMA16816(d, a, b0r, b1r) \
    asm volatile("mma.sync.aligned.m16n8k16.row.col.f32.bf16.bf16.f32 " \
        "{%0,%1,%2,%3}, {%4,%5,%6,%7}, {%8,%9}, {%0,%1,%2,%3};" \
        : "+f"((d)[0]), "+f"((d)[1]), "+f"((d)[2]), "+f"((d)[3]) \
        : "r"((a)[0]), "r"((a)[1]), "r"((a)[2]), "r"((a)[3]), \
          "r"(b0r), "r"(b1r))
#define FMA2(accv, av, bv) \
    asm("fma.rn.f32x2 %0, %1, %2, %0;" : "+l"(accv) : "l"(av), "l"(bv))
__device__ __forceinline__ float2 unpack2(unsigned long long v) {
    union { unsigned long long u; float2 f; } c; c.u = v; return c.f;
}
__device__ __forceinline__ unsigned long long packf2(float x, float y) {
    unsigned long long r;
    asm("mov.b64 %0, {%1, %2};" : "=l"(r) : "f"(x), "f"(y));
    return r;
}
__device__ __forceinline__ unsigned pack_bf16x2(float x, float y) {
    __nv_bfloat162 t = __floats2bfloat162_rn(x, y);   // .x low, .y high
    return *(unsigned*)&t;
}

// ---------------------------------------------------------------------------
// persistent scratch
// ---------------------------------------------------------------------------
// B stage images: [p][stage 0..7][32768B]; stage = chunk*2 + split
// stage layout: 256 n-rows x 64 k-cols bf16 (128B rows), off ^= (n&7)<<4
__device__ __align__(16) unsigned char g_Bimg[NSTAGES * 32768];
__device__ float g_W1r [PPARTS * 9 * 256];
__device__ float g_b1eff[PPARTS * 256];
__device__ float g_W3 [PPARTS * RTOT * 256];   // [p][r][d], r=20 is Wocc
__device__ float g_b3 [PPARTS * 24];

// ---------------------------------------------------------------------------
// prep kernels
// ---------------------------------------------------------------------------
__global__ void prep_small(const float* __restrict__ W1, const float* __restrict__ b1,
                           const float* __restrict__ W3, const float* __restrict__ b3,
                           const float* __restrict__ Wocc, const float* __restrict__ bocc,
                           const float* __restrict__ frame) {
    int p = blockIdx.x, d = threadIdx.x;
    const int rows[9] = {0, 1, 2, 11, 12, 13, 14, 15, 16};
    float be = b1[p * 256 + d];
#pragma unroll
    for (int f = 0; f < 8; ++f)
        be += frame[f] * W1[(p * 17 + 3 + f) * 256 + d];
    g_b1eff[p * 256 + d] = be;
#pragma unroll
    for (int i = 0; i < 9; ++i)
        g_W1r[(p * 9 + i) * 256 + d] = W1[(p * 17 + rows[i]) * 256 + d];
    for (int r = 0; r < 20; ++r)
        g_W3[(p * RTOT + r) * 256 + d] = W3[(p * 256 + d) * 20 + r];
    g_W3[(p * RTOT + 20) * 256 + d] = Wocc[p * 256 + d];
    if (d < 20)  g_b3[p * 24 + d]  = b3[p * 20 + d];
    if (d == 20) g_b3[p * 24 + 20] = bocc[p];
    if (d > 20 && d < 24) g_b3[p * 24 + d] = 0.f;
}

// Bs[n][kk] = W2[p][k][n], hi/lo bf16, swizzled 128B-row images.
__global__ void prep_B(const float* __restrict__ W2) {
    int p = blockIdx.x, k = blockIdx.y, n = threadIdx.x;
    float w = W2[((size_t)(p * 256 + k)) * 256 + n];
    __nv_bfloat16 hi = __float2bfloat16(w);
    __nv_bfloat16 lo = __float2bfloat16(w - __bfloat162float(hi));
    int chunk = k >> 6, kk = k & 63;
    unsigned off = (unsigned)(n * 128 + kk * 2);
    off ^= (unsigned)((n & 7) << 4);
    unsigned char* base = g_Bimg + ((size_t)(p * 8 + chunk * 2)) * 32768;
    *(__nv_bfloat16*)(base + off)         = hi;
    *(__nv_bfloat16*)(base + 32768 + off) = lo;
}

// ---------------------------------------------------------------------------
// main fused kernel
// ---------------------------------------------------------------------------
__device__ __forceinline__ void prefetch_stage(unsigned sbB, int tid, int g) {
    const unsigned char* src = g_Bimg + (size_t)g * 32768 + tid * 16;
    unsigned dst = sbB + (unsigned)((g & 1) * 32768 + tid * 16);
#pragma unroll
    for (int j = 0; j < 8; ++j)
        asm volatile("cp.async.cg.shared.global [%0], [%1], 16;"
                     :: "r"(dst + j * 4096), "l"(src + j * 4096));
    asm volatile("cp.async.commit_group;" ::: "memory");
}

__global__ void __launch_bounds__(THREADS, 1)
fused_kernel(const float* __restrict__ tpts,
             const float* __restrict__ bigpts,
             const float* __restrict__ viewdir,
             const float* __restrict__ b2g,
             const int* __restrict__ tflag,
             float* __restrict__ out) {
    extern __shared__ unsigned char smc[];
    const int tid  = threadIdx.x;
    const int lane = tid & 31;
    const int wid  = tid >> 5;
    const int wy   = wid >> 2;          // 0..1  (m tile of 32)
    const int wx   = wid & 3;           // 0..3  (n tile of 64)
    const int n0   = blockIdx.x * TM;

    const unsigned sb  = smem_to_u32(smc);
    const unsigned sbB = sb + OFF_B;
    const unsigned ahi = sb + OFF_A;
    const unsigned alo = sb + OFF_A + 32768;

    // ---- per-lane ldmatrix address bases ----
    unsigned a_rb[2], a_msk[2];
#pragma unroll
    for (int mt = 0; mt < 2; ++mt) {
        int ml = wy * 32 + mt * 16 + (lane & 15);
        a_rb[mt]  = (unsigned)(ml * 512 + (lane >> 4) * 16);
        a_msk[mt] = (unsigned)((ml & 7) << 4);
    }
    unsigned b_rb[4], b_msk[4];
#pragma unroll
    for (int t = 0; t < 4; ++t) {
        int n = wx * 64 + t * 16 + (lane & 7) + ((lane & 16) ? 8 : 0);
        b_rb[t]  = (unsigned)(n * 128 + ((lane & 8) ? 16 : 0));
        b_msk[t] = (unsigned)((n & 7) << 4);
    }

    // layer-3 mapping (R3-proven)
    const int mm = tid >> 2, rg = tid & 3, rbase = rg * 6;
    float accP[6] = {0.f, 0.f, 0.f, 0.f, 0.f, 0.f};

    // prologue prefetch: part 0, stage 0
    prefetch_stage(sbB, tid, 0);

    for (int p = 0; p < PPARTS; ++p) {
        // ---------------- stage per-part tables ----------------
        {
            float* w3s = (float*)(smc + OFF_W3);
            for (int idx = tid; idx < 24 * 256; idx += THREADS) {
                int r = idx >> 8, d = idx & 255;
                w3s[r * 260 + d] = (r < RTOT) ? g_W3[(p * RTOT + r) * 256 + d] : 0.f;
            }
            ((float*)(smc + OFF_B2))[tid]  = b2g[p * 256 + tid];
            ((float*)(smc + OFF_B1E))[tid] = g_b1eff[p * 256 + tid];
            float* w1s = (float*)(smc + OFF_W1R);
            for (int idx = tid; idx < 9 * 256; idx += THREADS)
                w1s[idx] = g_W1r[p * 9 * 256 + idx];
            if (tid < 24) ((float*)(smc + OFF_B3))[tid] = g_b3[p * 24 + tid];
            if (tid < TM)
                ((float*)(smc + OFF_FLAG))[tid] =
                    (tflag[(n0 + tid) * PPARTS + p] != 0) ? 1.f : 0.f;
        }

        // ---------------- layer 1: thread = (m, d-chunk of 64) ----
        {
            const int m1 = tid & 63;
            const int dc = tid >> 6;
            const int gi = (n0 + m1) * PPARTS + p;
            float x[9];
            x[0] = tpts[gi*3];    x[1] = tpts[gi*3+1];    x[2] = tpts[gi*3+2];
            x[3] = bigpts[gi*3];  x[4] = bigpts[gi*3+1];  x[5] = bigpts[gi*3+2];
            x[6] = viewdir[gi*3]; x[7] = viewdir[gi*3+1]; x[8] = viewdir[gi*3+2];
            __syncthreads();   // tables staged (also: prev part's layer3 done)

            const float* w1  = (const float*)(smc + OFF_W1R);
            const float* b1e = (const float*)(smc + OFF_B1E);
            const unsigned amask = (unsigned)((m1 & 7) << 4);
            const unsigned mrow  = (unsigned)(m1 * 512 + dc * 128);
#pragma unroll 4
            for (int gq = 0; gq < 16; ++gq) {
                const int d = dc * 64 + gq * 4;
                float4 a = *(const float4*)(b1e + d);
#pragma unroll
                for (int i = 0; i < 9; ++i) {
                    float4 w = *(const float4*)(w1 + i * 256 + d);
                    a.x += x[i]*w.x; a.y += x[i]*w.y;
                    a.z += x[i]*w.z; a.w += x[i]*w.w;
                }
                a.x = fmaxf(a.x, 0.f); a.y = fmaxf(a.y, 0.f);
                a.z = fmaxf(a.z, 0.f); a.w = fmaxf(a.w, 0.f);
                float hx = __bfloat162float(__float2bfloat16(a.x));
                float hy = __bfloat162float(__float2bfloat16(a.y));
                float hz = __bfloat162float(__float2bfloat16(a.z));
                float hw = __bfloat162float(__float2bfloat16(a.w));
                unsigned hi0 = pack_bf16x2(a.x, a.y);
                unsigned hi1 = pack_bf16x2(a.z, a.w);
                unsigned lo0 = pack_bf16x2(a.x - hx, a.y - hy);
                unsigned lo1 = pack_bf16x2(a.z - hz, a.w - hw);
                unsigned o0 = (mrow + gq * 8) ^ amask;
                unsigned o1 = (mrow + gq * 8 + 4) ^ amask;
                *(unsigned*)(smc + OFF_A + o0)         = hi0;
                *(unsigned*)(smc + OFF_A + o1)         = hi1;
                *(unsigned*)(smc + OFF_A + 32768 + o0) = lo0;
                *(unsigned*)(smc + OFF_A + 32768 + o1) = lo1;
            }
        }
        __syncthreads();   // A planes ready

        // ---------------- layer 2: 8 B-stages, MMA ----------------
        float acc[2][8][4];
#pragma unroll
        for (int mt = 0; mt < 2; ++mt)
#pragma unroll
            for (int nt = 0; nt < 8; ++nt)
#pragma unroll
                for (int q = 0; q < 4; ++q) acc[mt][nt][q] = 0.f;

#pragma unroll 1
        for (int s = 0; s < 8; ++s) {
            const int g = p * 8 + s;
            if (g + 1 < NSTAGES) {
                prefetch_stage(sbB, tid, g + 1);
                asm volatile("cp.async.wait_group 1;" ::: "memory");
            } else {
                asm volatile("cp.async.wait_group 0;" ::: "memory");
            }
            __syncthreads();   // stage g visible to all

            const unsigned slot  = sbB + (unsigned)((g & 1) * 32768);
            const unsigned acol0 = (unsigned)((s >> 1) * 128);

            if ((s & 1) == 0) {
                // B_hi stage: chains hi*hi and lo*hi
#pragma unroll
                for (int ks = 0; ks < 4; ++ks) {
                    const unsigned co = acol0 + ks * 32;
                    unsigned ah[2][4], al[2][4], bb[4][4];
                    LDSM4(ah[0], ahi + ((a_rb[0] + co) ^ a_msk[0]));
                    LDSM4(ah[1], ahi + ((a_rb[1] + co) ^ a_msk[1]));
                    LDSM4(al[0], alo + ((a_rb[0] + co) ^ a_msk[0]));
                    LDSM4(al[1], alo + ((a_rb[1] + co) ^ a_msk[1]));
#pragma unroll
                    for (int t = 0; t < 4; ++t)
                        LDSM4(bb[t], slot + ((b_rb[t] + ks * 32) ^ b_msk[t]));
#pragma unroll
                    for (int mt = 0; mt < 2; ++mt)
#pragma unroll
                        for (int t = 0; t < 4; ++t) {
                            MMA16816(acc[mt][2*t],   ah[mt], bb[t][0], bb[t][1]);
                            MMA16816(acc[mt][2*t+1], ah[mt], bb[t][2], bb[t][3]);
                            MMA16816(acc[mt][2*t],   al[mt], bb[t][0], bb[t][1]);
                            MMA16816(acc[mt][2*t+1], al[mt], bb[t][2], bb[t][3]);
                        }
                }
            } else {
                // B_lo stage: chain hi*lo
#pragma unroll
                for (int ks = 0; ks < 4; ++ks) {
                    const unsigned co = acol0 + ks * 32;
                    unsigned ah[2][4], bb[4][4];
                    LDSM4(ah[0], ahi + ((a_rb[0] + co) ^ a_msk[0]));
                    LDSM4(ah[1], ahi + ((a_rb[1] + co) ^ a_msk[1]));
#pragma unroll
                    for (int t = 0; t < 4; ++t)
                        LDSM4(bb[t], slot + ((b_rb[t] + ks * 32) ^ b_msk[t]));
#pragma unroll
                    for (int mt = 0; mt < 2; ++mt)
#pragma unroll
                        for (int t = 0; t < 4; ++t) {
                            MMA16816(acc[mt][2*t],   ah[mt], bb[t][0], bb[t][1]);
                            MMA16816(acc[mt][2*t+1], ah[mt], bb[t][2], bb[t][3]);
                        }
                }
            }
            __syncthreads();   // done reading slot before next prefetch reuses it
        }

        // ---------------- epilogue: acc -> h2 smem (+b2, relu) ----
        {
            const int er = (lane & 3) * 2;
            const int mr = lane >> 2;
            const float* b2s = (const float*)(smc + OFF_B2);
#pragma unroll
            for (int mt = 0; mt < 2; ++mt) {
                float* h2r0 = (float*)(smc + OFF_H2) + (wy * 32 + mt * 16 + mr) * 260;
                float* h2r1 = h2r0 + 8 * 260;
#pragma unroll
                for (int nt = 0; nt < 8; ++nt) {
                    const int e = wx * 64 + nt * 8 + er;
                    float2 bv = *(const float2*)(b2s + e);
                    float2 v01 = make_float2(fmaxf(acc[mt][nt][0] + bv.x, 0.f),
                                             fmaxf(acc[mt][nt][1] + bv.y, 0.f));
                    float2 v23 = make_float2(fmaxf(acc[mt][nt][2] + bv.x, 0.f),
                                             fmaxf(acc[mt][nt][3] + bv.y, 0.f));
                    *(float2*)(h2r0 + e) = v01;
                    *(float2*)(h2r1 + e) = v23;
                }
            }
        }
        __syncthreads();   // h2 ready

        // ---------------- layer 3 (R3-proven FFMA2) ----------------
        {
            const float* hrow  = (const float*)(smc + OFF_H2) + mm * 260;
            const float* wbase = (const float*)(smc + OFF_W3) + rbase * 260;
            unsigned long long a6[6] = {0ull, 0ull, 0ull, 0ull, 0ull, 0ull};
#pragma unroll 4
            for (int d = 0; d < 256; d += 4) {
                ulonglong2 h2v = *(const ulonglong2*)(hrow + d);
#pragma unroll
                for (int j = 0; j < 6; ++j) {
                    ulonglong2 wv = *(const ulonglong2*)(wbase + j * 260 + d);
                    FMA2(a6[j], h2v.x, wv.x);
                    FMA2(a6[j], h2v.y, wv.y);
                }
            }
            const float flagv = ((const float*)(smc + OFF_FLAG))[mm];
            const float* b3s = (const float*)(smc + OFF_B3);
#pragma unroll
            for (int j = 0; j < 6; ++j) {
                float2 c = unpack2(a6[j]);
                float v = c.x + c.y + b3s[rbase + j];
                if (rbase + j == 20) {
                    v = 1.f / (1.f + __expf(-v));
                    v *= flagv;
                    out[(size_t)(n0 + mm) * OUTC + 21 + p] = v;  // tocc
                } else {
                    v *= flagv;
                }
                accP[j] += v;
            }
        }
        __syncthreads();   // protect smem (h2/A alias, tables) for next part
    }

    // ---------------- final masked means ----------------
    const float inv6 = 1.f / 6.f;
#pragma unroll
    for (int j = 0; j < 6; ++j) {
        int r = rbase + j;
        if (r < RTOT)
            out[(size_t)(n0 + mm) * OUTC + r] = accP[j] * inv6;
    }
}

// ---------------------------------------------------------------------------
// launch
// ---------------------------------------------------------------------------
extern "C" void kernel_launch(void* const* d_in, const int* in_sizes, int n_in,
                              void* d_out, int out_size) {
    const float* tpts    = (const float*)d_in[0];
    const float* bigpts  = (const float*)d_in[1];
    const float* viewdir = (const float*)d_in[2];
    // d_in[3]=dists, d_in[4]=part_dist unused
    const float* frame   = (const float*)d_in[5];
    const float* W1      = (const float*)d_in[6];
    const float* b1      = (const float*)d_in[7];
    const float* W2      = (const float*)d_in[8];
    const float* b2      = (const float*)d_in[9];
    const float* W3      = (const float*)d_in[10];
    const float* b3      = (const float*)d_in[11];
    const float* Wocc    = (const float*)d_in[12];
    const float* bocc    = (const float*)d_in[13];
    const int*   tflag   = (const int*)d_in[14];
    float* out = (float*)d_out;

    prep_small<<<PPARTS, 256>>>(W1, b1, W3, b3, Wocc, bocc, frame);
    prep_B<<<dim3(PPARTS, 256), 256>>>(W2);

    cudaFuncSetAttribute(fused_kernel,
                         cudaFuncAttributeMaxDynamicSharedMemorySize,
                         SMEM_BYTES);
    fused_kernel<<<NCTAS, THREADS, SMEM_BYTES>>>(tpts, bigpts, viewdir,
                                                 b2, tflag, out);
}

// round 7
// speedup vs baseline: 2.2705x; 1.5048x over previous
#include <cuda_runtime.h>
#include <cuda_bf16.h>

// ---------------------------------------------------------------------------
// TPoseHuman fused 6-part MLP — layers 2 AND 3 on mma.sync bf16 (3-chain
// hi/lo error compensation). 2 CTAs/SM (97KB smem), all weight streams via
// cp.async 2-slot ring of uniform 16KB stages (16 layer2 + 2 layer3 / part).
//   layer1: scalar fp32 -> bf16 hi/lo A planes in smem
//   layer2: D(64x256 f32, regs) += A x B(W2^T hi/lo)
//   epilogue: D + b2, relu -> bf16 hi/lo h2 planes (alias A planes)
//   layer3: D3(64x32 f32, regs) += h2 x W3img(hi/lo); mask/sigmoid/mean in regs
// ---------------------------------------------------------------------------

#define NPTS    65536
#define PPARTS  6
#define TM      64
#define NCTAS   (NPTS / TM)       // 1024
#define THREADS 256
#define OUTC    27
#define SPP     18                // stages per part: 16 layer2 + 2 layer3
#define NSTG    (PPARTS * SPP)    // 108

// ---- smem byte offsets ----
#define OFF_RING 0u               // 2 x 16384
#define OFF_AHI  32768u           // 64 rows x 512B (A hi / h2 hi)
#define OFF_ALO  65536u           // 64 rows x 512B (A lo / h2 lo)
#define SMEM_BYTES 98304

// ---------------------------------------------------------------------------
// asm helpers (baseline PTX, sm_80-era: family-safe on compute_103)
// ---------------------------------------------------------------------------
__device__ __forceinline__ unsigned smem_to_u32(const void* p) {
    unsigned a;
    asm("{ .reg .u64 t; cvta.to.shared.u64 t, %1; cvt.u32.u64 %0, t; }"
        : "=r"(a) : "l"(p));
    return a;
}
#define LDSM4(r, addr) \
    asm volatile("ldmatrix.sync.aligned.m8n8.x4.shared.b16 {%0,%1,%2,%3}, [%4];" \
        : "=r"((r)[0]), "=r"((r)[1]), "=r"((r)[2]), "=r"((r)[3]) : "r"(addr))
#define MMA16816(d, a, b0r, b1r) \
    asm volatile("mma.sync.aligned.m16n8k16.row.col.f32.bf16.bf16.f32 " \
        "{%0,%1,%2,%3}, {%4,%5,%6,%7}, {%8,%9}, {%0,%1,%2,%3};" \
        : "+f"((d)[0]), "+f"((d)[1]), "+f"((d)[2]), "+f"((d)[3]) \
        : "r"((a)[0]), "r"((a)[1]), "r"((a)[2]), "r"((a)[3]), \
          "r"(b0r), "r"(b1r))
__device__ __forceinline__ unsigned pack_bf16x2(float x, float y) {
    __nv_bfloat162 t = __floats2bfloat162_rn(x, y);
    return *(unsigned*)&t;
}

// ---------------------------------------------------------------------------
// persistent scratch
// ---------------------------------------------------------------------------
// Uniform 16KB stages: per part, stages 0..15 = W2^T k-chunks (hi,lo pairs),
// stages 16,17 = W3img (hi,lo). 64B-row layout, swizzle off ^= ((n>>1)&3)<<4.
__device__ __align__(16) unsigned char g_Bimg[NSTG * 16384];
__device__ __align__(16) float g_W1r  [PPARTS * 9 * 256];
__device__ __align__(16) float g_b1eff[PPARTS * 256];
__device__ __align__(16) float g_b3   [PPARTS * 32];

// ---------------------------------------------------------------------------
// prep kernels
// ---------------------------------------------------------------------------
__global__ void prep_small(const float* __restrict__ W1, const float* __restrict__ b1,
                           const float* __restrict__ b3, const float* __restrict__ bocc,
                           const float* __restrict__ frame) {
    int p = blockIdx.x, d = threadIdx.x;
    const int rows[9] = {0, 1, 2, 11, 12, 13, 14, 15, 16};
    float be = b1[p * 256 + d];
#pragma unroll
    for (int f = 0; f < 8; ++f)
        be += frame[f] * W1[(p * 17 + 3 + f) * 256 + d];
    g_b1eff[p * 256 + d] = be;
#pragma unroll
    for (int i = 0; i < 9; ++i)
        g_W1r[(p * 9 + i) * 256 + d] = W1[(p * 17 + rows[i]) * 256 + d];
    if (d < 32) {
        float v = 0.f;
        if (d < 20)  v = b3[p * 20 + d];
        if (d == 20) v = bocc[p];
        g_b3[p * 32 + d] = v;
    }
}

// layer2 B images: Bs[n][k] = W2[p][k][n], hi/lo bf16, 64B-row swizzled stages
__global__ void prep_B2(const float* __restrict__ W2) {
    int p = blockIdx.x, k = blockIdx.y, n = threadIdx.x;
    float w = W2[((size_t)(p * 256 + k)) * 256 + n];
    __nv_bfloat16 hi = __float2bfloat16(w);
    __nv_bfloat16 lo = __float2bfloat16(w - __bfloat162float(hi));
    int s_hi = (k >> 5) * 2;                       // stage pair for this k-window
    unsigned off = (unsigned)(n * 64 + ((k >> 4) & 1) * 32 + (k & 15) * 2);
    off ^= (unsigned)(((n >> 1) & 3) << 4);
    unsigned char* base = g_Bimg + ((size_t)(p * SPP + s_hi)) * 16384;
    *(__nv_bfloat16*)(base + off)         = hi;
    *(__nv_bfloat16*)(base + 16384 + off) = lo;
}

// layer3 B images: B3[n][k] = [W3|Wocc|0pad]^T, n 0..31, k 0..255
__global__ void prep_B3(const float* __restrict__ W3,
                        const float* __restrict__ Wocc) {
    int p = blockIdx.x, k = blockIdx.y, n = threadIdx.x;   // n < 32
    float w = 0.f;
    if (n < 20)  w = W3[((size_t)(p * 256 + k)) * 20 + n];
    if (n == 20) w = Wocc[p * 256 + k];
    __nv_bfloat16 hi = __float2bfloat16(w);
    __nv_bfloat16 lo = __float2bfloat16(w - __bfloat162float(hi));
    unsigned off = (unsigned)((k >> 5) * 2048 + n * 64 +
                              ((k >> 4) & 1) * 32 + (k & 15) * 2);
    off ^= (unsigned)(((n >> 1) & 3) << 4);
    unsigned char* base = g_Bimg + ((size_t)(p * SPP + 16)) * 16384;
    *(__nv_bfloat16*)(base + off)         = hi;
    *(__nv_bfloat16*)(base + 16384 + off) = lo;
}

// ---------------------------------------------------------------------------
// main fused kernel
// ---------------------------------------------------------------------------
__device__ __forceinline__ void prefetch_stage(unsigned ring, int tid, int g) {
    const unsigned char* src = g_Bimg + (size_t)g * 16384 + tid * 16;
    unsigned dst = ring + (unsigned)((g & 1) * 16384 + tid * 16);
#pragma unroll
    for (int j = 0; j < 4; ++j)
        asm volatile("cp.async.cg.shared.global [%0], [%1], 16;"
                     :: "r"(dst + j * 4096), "l"(src + j * 4096));
    asm volatile("cp.async.commit_group;" ::: "memory");
}

__global__ void __launch_bounds__(THREADS, 2)
fused_kernel(const float* __restrict__ tpts,
             const float* __restrict__ bigpts,
             const float* __restrict__ viewdir,
             const float* __restrict__ b2g,
             const int* __restrict__ tflag,
             float* __restrict__ out) {
    extern __shared__ unsigned char smc[];
    const int tid  = threadIdx.x;
    const int lane = tid & 31;
    const int wid  = tid >> 5;
    const int wy   = wid >> 2;          // layer2: m tile of 32
    const int wx   = wid & 3;           // layer2: n tile of 64
    const int n0   = blockIdx.x * TM;

    const unsigned sb   = smem_to_u32(smc);
    const unsigned ring = sb + OFF_RING;

    // ---- layer2 ldmatrix bases (validated in R6) ----
    unsigned a_rb[2], a_msk[2];
#pragma unroll
    for (int mt = 0; mt < 2; ++mt) {
        int ml = wy * 32 + mt * 16 + (lane & 15);
        a_rb[mt]  = (unsigned)(ml * 512 + (lane >> 4) * 16);
        a_msk[mt] = (unsigned)((ml & 7) << 4);
    }
    unsigned b_off[4], b_sw[4];
#pragma unroll
    for (int t = 0; t < 4; ++t) {
        int n = wx * 64 + t * 16 + (lane & 7) + ((lane & 16) ? 8 : 0);
        b_off[t] = (unsigned)(n * 64 + ((lane & 8) ? 16 : 0));
        b_sw[t]  = (unsigned)(((n >> 1) & 3) << 4);
    }
    // ---- layer3 bases: warp w -> m-tile (w>>1), n-half (w&1) ----
    const int ml3 = (wid >> 1) * 16 + (lane & 15);
    const unsigned a3_rb  = (unsigned)(ml3 * 512 + (lane >> 4) * 16);
    const unsigned a3_msk = (unsigned)((ml3 & 7) << 4);
    const int n3 = (wid & 1) * 16 + (lane & 7) + ((lane & 16) ? 8 : 0);
    const unsigned b3_off = (unsigned)(n3 * 64 + ((lane & 8) ? 16 : 0));
    const unsigned b3_sw  = (unsigned)(((n3 >> 1) & 3) << 4);
    const int r0 = (wid >> 1) * 16 + (lane >> 2);
    const int r1 = r0 + 8;
    const int cbase = (wid & 1) * 16 + (lane & 3) * 2;

    float sums[2][4];
#pragma unroll
    for (int t = 0; t < 2; ++t)
#pragma unroll
        for (int q = 0; q < 4; ++q) sums[t][q] = 0.f;

    prefetch_stage(ring, tid, 0);

    for (int p = 0; p < PPARTS; ++p) {
        // ---------------- layer 1 (thread = (m, d-chunk of 64)) ----------
        {
            const int m1 = tid & 63;
            const int dc = tid >> 6;
            const int gi = (n0 + m1) * PPARTS + p;
            float x[9];
            x[0] = tpts[gi*3];    x[1] = tpts[gi*3+1];    x[2] = tpts[gi*3+2];
            x[3] = bigpts[gi*3];  x[4] = bigpts[gi*3+1];  x[5] = bigpts[gi*3+2];
            x[6] = viewdir[gi*3]; x[7] = viewdir[gi*3+1]; x[8] = viewdir[gi*3+2];
            const float* w1  = g_W1r + p * 2304;
            const float* b1e = g_b1eff + p * 256;
            const unsigned amask = (unsigned)((m1 & 7) << 4);
            const unsigned mrow  = (unsigned)(m1 * 512 + dc * 128);
#pragma unroll 4
            for (int gq = 0; gq < 16; ++gq) {
                const int d = dc * 64 + gq * 4;
                float4 a = *(const float4*)(b1e + d);
#pragma unroll
                for (int i = 0; i < 9; ++i) {
                    float4 w = *(const float4*)(w1 + i * 256 + d);
                    a.x += x[i]*w.x; a.y += x[i]*w.y;
                    a.z += x[i]*w.z; a.w += x[i]*w.w;
                }
                a.x = fmaxf(a.x, 0.f); a.y = fmaxf(a.y, 0.f);
                a.z = fmaxf(a.z, 0.f); a.w = fmaxf(a.w, 0.f);
                float hx = __bfloat162float(__float2bfloat16(a.x));
                float hy = __bfloat162float(__float2bfloat16(a.y));
                float hz = __bfloat162float(__float2bfloat16(a.z));
                float hw = __bfloat162float(__float2bfloat16(a.w));
                unsigned o0 = (mrow + gq * 8) ^ amask;
                unsigned o1 = (mrow + gq * 8 + 4) ^ amask;
                *(unsigned*)(smc + OFF_AHI + o0) = pack_bf16x2(a.x, a.y);
                *(unsigned*)(smc + OFF_AHI + o1) = pack_bf16x2(a.z, a.w);
                *(unsigned*)(smc + OFF_ALO + o0) = pack_bf16x2(a.x - hx, a.y - hy);
                *(unsigned*)(smc + OFF_ALO + o1) = pack_bf16x2(a.z - hz, a.w - hw);
            }
        }
        __syncthreads();   // A planes ready (prev part fully done: stage-17 end sync)

        float acc[2][8][4];
#pragma unroll
        for (int mt = 0; mt < 2; ++mt)
#pragma unroll
            for (int nt = 0; nt < 8; ++nt)
#pragma unroll
                for (int q = 0; q < 4; ++q) acc[mt][nt][q] = 0.f;
        float acc3[2][4];
#pragma unroll
        for (int t = 0; t < 2; ++t)
#pragma unroll
            for (int q = 0; q < 4; ++q) acc3[t][q] = 0.f;

#pragma unroll 1
        for (int s = 0; s < SPP; ++s) {
            // -------- epilogue between layer2 and layer3 stages --------
            if (s == 16) {
                // acc -> h2 bf16 hi/lo planes (overwrite A planes).
                // All warps passed stage-15 end sync; visibility to other
                // warps is ordered by the post-wait sync below.
#pragma unroll
                for (int mt = 0; mt < 2; ++mt) {
                    const int row0 = wy * 32 + mt * 16 + (lane >> 2);
#pragma unroll
                    for (int nt = 0; nt < 8; ++nt) {
                        const int e = wx * 64 + nt * 8 + (lane & 3) * 2;
                        float2 bv = *(const float2*)(b2g + p * 256 + e);
                        float v0 = fmaxf(acc[mt][nt][0] + bv.x, 0.f);
                        float v1 = fmaxf(acc[mt][nt][1] + bv.y, 0.f);
                        float v2 = fmaxf(acc[mt][nt][2] + bv.x, 0.f);
                        float v3 = fmaxf(acc[mt][nt][3] + bv.y, 0.f);
                        float h0 = __bfloat162float(__float2bfloat16(v0));
                        float h1 = __bfloat162float(__float2bfloat16(v1));
                        float h2 = __bfloat162float(__float2bfloat16(v2));
                        float h3 = __bfloat162float(__float2bfloat16(v3));
                        unsigned o0 = (unsigned)(row0 * 512 + e * 2) ^
                                      (unsigned)((row0 & 7) << 4);
                        unsigned o1 = (unsigned)((row0 + 8) * 512 + e * 2) ^
                                      (unsigned)(((row0 + 8) & 7) << 4);
                        *(unsigned*)(smc + OFF_AHI + o0) = pack_bf16x2(v0, v1);
                        *(unsigned*)(smc + OFF_ALO + o0) = pack_bf16x2(v0 - h0, v1 - h1);
                        *(unsigned*)(smc + OFF_AHI + o1) = pack_bf16x2(v2, v3);
                        *(unsigned*)(smc + OFF_ALO + o1) = pack_bf16x2(v2 - h2, v3 - h3);
                    }
                }
            }

            const int g = p * SPP + s;
            if (g + 1 < NSTG) {
                prefetch_stage(ring, tid, g + 1);
                asm volatile("cp.async.wait_group 1;" ::: "memory");
            } else {
                asm volatile("cp.async.wait_group 0;" ::: "memory");
            }
            __syncthreads();   // stage g visible (and epilogue writes, when s==16)

            const unsigned slot = ring + (unsigned)((g & 1) * 16384);

            if (s < 16) {
                // ---------------- layer2 stage: k-window s>>1 ----------
                const unsigned cw = (unsigned)((s >> 1) * 64);
                if ((s & 1) == 0) {
#pragma unroll
                    for (int ks2 = 0; ks2 < 2; ++ks2) {
                        const unsigned cc = cw + ks2 * 32;
                        unsigned ah[2][4], al[2][4], bb[4][4];
                        LDSM4(ah[0], sb + OFF_AHI + ((a_rb[0] + cc) ^ a_msk[0]));
                        LDSM4(ah[1], sb + OFF_AHI + ((a_rb[1] + cc) ^ a_msk[1]));
                        LDSM4(al[0], sb + OFF_ALO + ((a_rb[0] + cc) ^ a_msk[0]));
                        LDSM4(al[1], sb + OFF_ALO + ((a_rb[1] + cc) ^ a_msk[1]));
#pragma unroll
                        for (int t = 0; t < 4; ++t)
                            LDSM4(bb[t], slot + ((b_off[t] + ks2 * 32) ^ b_sw[t]));
#pragma unroll
                        for (int mt = 0; mt < 2; ++mt)
#pragma unroll
                            for (int t = 0; t < 4; ++t) {
                                MMA16816(acc[mt][2*t],   ah[mt], bb[t][0], bb[t][1]);
                                MMA16816(acc[mt][2*t+1], ah[mt], bb[t][2], bb[t][3]);
                                MMA16816(acc[mt][2*t],   al[mt], bb[t][0], bb[t][1]);
                                MMA16816(acc[mt][2*t+1], al[mt], bb[t][2], bb[t][3]);
                            }
                    }
                } else {
#pragma unroll
                    for (int ks2 = 0; ks2 < 2; ++ks2) {
                        const unsigned cc = cw + ks2 * 32;
                        unsigned ah[2][4], bb[4][4];
                        LDSM4(ah[0], sb + OFF_AHI + ((a_rb[0] + cc) ^ a_msk[0]));
                        LDSM4(ah[1], sb + OFF_AHI + ((a_rb[1] + cc) ^ a_msk[1]));
#pragma unroll
                        for (int t = 0; t < 4; ++t)
                            LDSM4(bb[t], slot + ((b_off[t] + ks2 * 32) ^ b_sw[t]));
#pragma unroll
                        for (int mt = 0; mt < 2; ++mt)
#pragma unroll
                            for (int t = 0; t < 4; ++t) {
                                MMA16816(acc[mt][2*t],   ah[mt], bb[t][0], bb[t][1]);
                                MMA16816(acc[mt][2*t+1], ah[mt], bb[t][2], bb[t][3]);
                            }
                    }
                }
            } else {
                // ---------------- layer3 stage (16=W3hi, 17=W3lo) ------
                const bool hi3 = (s == 16);
#pragma unroll
                for (int ks = 0; ks < 16; ++ks) {
                    const unsigned cc = (unsigned)(ks * 32);
                    unsigned ah[4], al[4], bb[4];
                    LDSM4(ah, sb + OFF_AHI + ((a3_rb + cc) ^ a3_msk));
                    if (hi3) LDSM4(al, sb + OFF_ALO + ((a3_rb + cc) ^ a3_msk));
                    LDSM4(bb, slot + (unsigned)((ks >> 1) * 2048) +
                              ((b3_off + (ks & 1) * 32) ^ b3_sw));
                    MMA16816(acc3[0], ah, bb[0], bb[1]);
                    MMA16816(acc3[1], ah, bb[2], bb[3]);
                    if (hi3) {
                        MMA16816(acc3[0], al, bb[0], bb[1]);
                        MMA16816(acc3[1], al, bb[2], bb[3]);
                    }
                }
            }
            __syncthreads();   // all warps done with slot before it is rewritten
        }

        // ---------------- extraction: mask, sigmoid, accumulate --------
        {
            const float fl0 = (tflag[(n0 + r0) * PPARTS + p] != 0) ? 1.f : 0.f;
            const float fl1 = (tflag[(n0 + r1) * PPARTS + p] != 0) ? 1.f : 0.f;
#pragma unroll
            for (int t = 0; t < 2; ++t) {
                const int c = cbase + t * 8;
                const float b3a = g_b3[p * 32 + c];
                const float b3b = g_b3[p * 32 + c + 1];
                float v0 = acc3[t][0] + b3a, v1 = acc3[t][1] + b3b;
                float v2 = acc3[t][2] + b3a, v3 = acc3[t][3] + b3b;
                if (c == 20) {
                    v0 = (1.f / (1.f + __expf(-v0))) * fl0;
                    v2 = (1.f / (1.f + __expf(-v2))) * fl1;
                    out[(size_t)(n0 + r0) * OUTC + 21 + p] = v0;   // tocc
                    out[(size_t)(n0 + r1) * OUTC + 21 + p] = v2;
                } else {
                    v0 *= fl0; v2 *= fl1;
                }
                v1 *= fl0; v3 *= fl1;
                sums[t][0] += v0; sums[t][1] += v1;
                sums[t][2] += v2; sums[t][3] += v3;
            }
        }
        __syncthreads();   // protect A/h2 planes before next part's layer1
    }

    // ---------------- final masked means ----------------
    const float inv6 = 1.f / 6.f;
#pragma unroll
    for (int t = 0; t < 2; ++t) {
        const int c = cbase + t * 8;
        if (c < 21) {
            out[(size_t)(n0 + r0) * OUTC + c] = sums[t][0] * inv6;
            out[(size_t)(n0 + r1) * OUTC + c] = sums[t][2] * inv6;
        }
        if (c + 1 < 21) {
            out[(size_t)(n0 + r0) * OUTC + c + 1] = sums[t][1] * inv6;
            out[(size_t)(n0 + r1) * OUTC + c + 1] = sums[t][3] * inv6;
        }
    }
}

// ---------------------------------------------------------------------------
// launch
// ---------------------------------------------------------------------------
extern "C" void kernel_launch(void* const* d_in, const int* in_sizes, int n_in,
                              void* d_out, int out_size) {
    const float* tpts    = (const float*)d_in[0];
    const float* bigpts  = (const float*)d_in[1];
    const float* viewdir = (const float*)d_in[2];
    // d_in[3]=dists, d_in[4]=part_dist unused
    const float* frame   = (const float*)d_in[5];
    const float* W1      = (const float*)d_in[6];
    const float* b1      = (const float*)d_in[7];
    const float* W2      = (const float*)d_in[8];
    const float* b2      = (const float*)d_in[9];
    const float* W3      = (const float*)d_in[10];
    const float* b3      = (const float*)d_in[11];
    const float* Wocc    = (const float*)d_in[12];
    const float* bocc    = (const float*)d_in[13];
    const int*   tflag   = (const int*)d_in[14];
    float* out = (float*)d_out;

    prep_small<<<PPARTS, 256>>>(W1, b1, b3, bocc, frame);
    prep_B2<<<dim3(PPARTS, 256), 256>>>(W2);
    prep_B3<<<dim3(PPARTS, 256), 32>>>(W3, Wocc);

    cudaFuncSetAttribute(fused_kernel,
                         cudaFuncAttributeMaxDynamicSharedMemorySize,
                         SMEM_BYTES);
    fused_kernel<<<NCTAS, THREADS, SMEM_BYTES>>>(tpts, bigpts, viewdir,
                                                 b2, tflag, out);
}

// round 8
// speedup vs baseline: 2.2961x; 1.0112x over previous
#include <cuda_runtime.h>
#include <cuda_bf16.h>

// ---------------------------------------------------------------------------
// TPoseHuman fused 6-part MLP — layers 2 AND 3 on mma.sync bf16 (3-chain
// hi/lo error compensation). 2 CTAs/SM (112KB smem), weight streams via
// cp.async 3-slot ring of uniform 16KB stages -> ONE barrier per stage.
//   layer1: scalar fp32 -> bf16 hi/lo A planes in smem
//   layer2: D(64x256 f32, regs) += A x B(W2^T hi/lo)
//   epilogue: D + b2, relu -> bf16 hi/lo h2 planes (alias A planes)
//   layer3: D3(64x32 f32, regs) += h2 x W3img(hi/lo); mask/sigmoid/mean in regs
// ---------------------------------------------------------------------------

#define NPTS    65536
#define PPARTS  6
#define TM      64
#define NCTAS   (NPTS / TM)       // 1024
#define THREADS 256
#define OUTC    27
#define SPP     18                // stages per part: 16 layer2 + 2 layer3
#define NSTG    (PPARTS * SPP)    // 108

// ---- smem byte offsets ----
#define OFF_RING 0u               // 3 x 16384 = 49152
#define OFF_AHI  49152u           // 64 rows x 512B (A hi / h2 hi)
#define OFF_ALO  81920u           // 64 rows x 512B (A lo / h2 lo)
#define SMEM_BYTES 114688         // 112 KB -> 2 CTAs/SM

// ---------------------------------------------------------------------------
// asm helpers (baseline PTX, sm_80-era: family-safe on compute_103)
// ---------------------------------------------------------------------------
__device__ __forceinline__ unsigned smem_to_u32(const void* p) {
    unsigned a;
    asm("{ .reg .u64 t; cvta.to.shared.u64 t, %1; cvt.u32.u64 %0, t; }"
        : "=r"(a) : "l"(p));
    return a;
}
#define LDSM4(r, addr) \
    asm volatile("ldmatrix.sync.aligned.m8n8.x4.shared.b16 {%0,%1,%2,%3}, [%4];" \
        : "=r"((r)[0]), "=r"((r)[1]), "=r"((r)[2]), "=r"((r)[3]) : "r"(addr))
#define MMA16816(d, a, b0r, b1r) \
    asm volatile("mma.sync.aligned.m16n8k16.row.col.f32.bf16.bf16.f32 " \
        "{%0,%1,%2,%3}, {%4,%5,%6,%7}, {%8,%9}, {%0,%1,%2,%3};" \
        : "+f"((d)[0]), "+f"((d)[1]), "+f"((d)[2]), "+f"((d)[3]) \
        : "r"((a)[0]), "r"((a)[1]), "r"((a)[2]), "r"((a)[3]), \
          "r"(b0r), "r"(b1r))
__device__ __forceinline__ unsigned pack_bf16x2(float x, float y) {
    __nv_bfloat162 t = __floats2bfloat162_rn(x, y);
    return *(unsigned*)&t;
}

// ---------------------------------------------------------------------------
// persistent scratch
// ---------------------------------------------------------------------------
// Uniform 16KB stages: per part, stages 0..15 = W2^T k-chunks (hi,lo pairs),
// stages 16,17 = W3img (hi,lo). 64B-row layout, swizzle off ^= ((n>>1)&3)<<4.
__device__ __align__(16) unsigned char g_Bimg[NSTG * 16384];
__device__ __align__(16) float g_W1r  [PPARTS * 9 * 256];
__device__ __align__(16) float g_b1eff[PPARTS * 256];
__device__ __align__(16) float g_b3   [PPARTS * 32];

// ---------------------------------------------------------------------------
// prep kernels
// ---------------------------------------------------------------------------
__global__ void prep_small(const float* __restrict__ W1, const float* __restrict__ b1,
                           const float* __restrict__ b3, const float* __restrict__ bocc,
                           const float* __restrict__ frame) {
    int p = blockIdx.x, d = threadIdx.x;
    const int rows[9] = {0, 1, 2, 11, 12, 13, 14, 15, 16};
    float be = b1[p * 256 + d];
#pragma unroll
    for (int f = 0; f < 8; ++f)
        be += frame[f] * W1[(p * 17 + 3 + f) * 256 + d];
    g_b1eff[p * 256 + d] = be;
#pragma unroll
    for (int i = 0; i < 9; ++i)
        g_W1r[(p * 9 + i) * 256 + d] = W1[(p * 17 + rows[i]) * 256 + d];
    if (d < 32) {
        float v = 0.f;
        if (d < 20)  v = b3[p * 20 + d];
        if (d == 20) v = bocc[p];
        g_b3[p * 32 + d] = v;
    }
}

// layer2 B images: Bs[n][k] = W2[p][k][n], hi/lo bf16, 64B-row swizzled stages
__global__ void prep_B2(const float* __restrict__ W2) {
    int p = blockIdx.x, k = blockIdx.y, n = threadIdx.x;
    float w = W2[((size_t)(p * 256 + k)) * 256 + n];
    __nv_bfloat16 hi = __float2bfloat16(w);
    __nv_bfloat16 lo = __float2bfloat16(w - __bfloat162float(hi));
    int s_hi = (k >> 5) * 2;                       // stage pair for this k-window
    unsigned off = (unsigned)(n * 64 + ((k >> 4) & 1) * 32 + (k & 15) * 2);
    off ^= (unsigned)(((n >> 1) & 3) << 4);
    unsigned char* base = g_Bimg + ((size_t)(p * SPP + s_hi)) * 16384;
    *(__nv_bfloat16*)(base + off)         = hi;
    *(__nv_bfloat16*)(base + 16384 + off) = lo;
}

// layer3 B images: B3[n][k] = [W3|Wocc|0pad]^T, n 0..31, k 0..255
__global__ void prep_B3(const float* __restrict__ W3,
                        const float* __restrict__ Wocc) {
    int p = blockIdx.x, k = blockIdx.y, n = threadIdx.x;   // n < 32
    float w = 0.f;
    if (n < 20)  w = W3[((size_t)(p * 256 + k)) * 20 + n];
    if (n == 20) w = Wocc[p * 256 + k];
    __nv_bfloat16 hi = __float2bfloat16(w);
    __nv_bfloat16 lo = __float2bfloat16(w - __bfloat162float(hi));
    unsigned off = (unsigned)((k >> 5) * 2048 + n * 64 +
                              ((k >> 4) & 1) * 32 + (k & 15) * 2);
    off ^= (unsigned)(((n >> 1) & 3) << 4);
    unsigned char* base = g_Bimg + ((size_t)(p * SPP + 16)) * 16384;
    *(__nv_bfloat16*)(base + off)         = hi;
    *(__nv_bfloat16*)(base + 16384 + off) = lo;
}

// ---------------------------------------------------------------------------
// main fused kernel
// ---------------------------------------------------------------------------
__device__ __forceinline__ void prefetch_stage(unsigned ring, int tid, int g) {
    const unsigned char* src = g_Bimg + (size_t)g * 16384 + tid * 16;
    unsigned dst = ring + (unsigned)((g % 3) * 16384 + tid * 16);
#pragma unroll
    for (int j = 0; j < 4; ++j)
        asm volatile("cp.async.cg.shared.global [%0], [%1], 16;"
                     :: "r"(dst + j * 4096), "l"(src + j * 4096));
    asm volatile("cp.async.commit_group;" ::: "memory");
}

__global__ void __launch_bounds__(THREADS, 2)
fused_kernel(const float* __restrict__ tpts,
             const float* __restrict__ bigpts,
             const float* __restrict__ viewdir,
             const float* __restrict__ b2g,
             const int* __restrict__ tflag,
             float* __restrict__ out) {
    extern __shared__ unsigned char smc[];
    const int tid  = threadIdx.x;
    const int lane = tid & 31;
    const int wid  = tid >> 5;
    const int wy   = wid >> 2;          // layer2: m tile of 32
    const int wx   = wid & 3;           // layer2: n tile of 64
    const int n0   = blockIdx.x * TM;

    const unsigned sb   = smem_to_u32(smc);
    const unsigned ring = sb + OFF_RING;

    // ---- layer2 ldmatrix bases (validated R6/R7) ----
    unsigned a_rb[2], a_msk[2];
#pragma unroll
    for (int mt = 0; mt < 2; ++mt) {
        int ml = wy * 32 + mt * 16 + (lane & 15);
        a_rb[mt]  = (unsigned)(ml * 512 + (lane >> 4) * 16);
        a_msk[mt] = (unsigned)((ml & 7) << 4);
    }
    unsigned b_off[4], b_sw[4];
#pragma unroll
    for (int t = 0; t < 4; ++t) {
        int n = wx * 64 + t * 16 + (lane & 7) + ((lane & 16) ? 8 : 0);
        b_off[t] = (unsigned)(n * 64 + ((lane & 8) ? 16 : 0));
        b_sw[t]  = (unsigned)(((n >> 1) & 3) << 4);
    }
    // ---- layer3 bases: warp w -> m-tile (w>>1), n-half (w&1) ----
    const int ml3 = (wid >> 1) * 16 + (lane & 15);
    const unsigned a3_rb  = (unsigned)(ml3 * 512 + (lane >> 4) * 16);
    const unsigned a3_msk = (unsigned)((ml3 & 7) << 4);
    const int n3 = (wid & 1) * 16 + (lane & 7) + ((lane & 16) ? 8 : 0);
    const unsigned b3_off = (unsigned)(n3 * 64 + ((lane & 8) ? 16 : 0));
    const unsigned b3_sw  = (unsigned)(((n3 >> 1) & 3) << 4);
    const int r0 = (wid >> 1) * 16 + (lane >> 2);
    const int r1 = r0 + 8;
    const int cbase = (wid & 1) * 16 + (lane & 3) * 2;

    float sums[2][4];
#pragma unroll
    for (int t = 0; t < 2; ++t)
#pragma unroll
        for (int q = 0; q < 4; ++q) sums[t][q] = 0.f;

    prefetch_stage(ring, tid, 0);

    for (int p = 0; p < PPARTS; ++p) {
        // ---------------- layer 1 (thread = (m, d-chunk of 64)) ----------
        {
            const int m1 = tid & 63;
            const int dc = tid >> 6;
            const int gi = (n0 + m1) * PPARTS + p;
            float x[9];
            x[0] = tpts[gi*3];    x[1] = tpts[gi*3+1];    x[2] = tpts[gi*3+2];
            x[3] = bigpts[gi*3];  x[4] = bigpts[gi*3+1];  x[5] = bigpts[gi*3+2];
            x[6] = viewdir[gi*3]; x[7] = viewdir[gi*3+1]; x[8] = viewdir[gi*3+2];
            const float* w1  = g_W1r + p * 2304;
            const float* b1e = g_b1eff + p * 256;
            const unsigned amask = (unsigned)((m1 & 7) << 4);
            const unsigned mrow  = (unsigned)(m1 * 512 + dc * 128);
#pragma unroll 4
            for (int gq = 0; gq < 16; ++gq) {
                const int d = dc * 64 + gq * 4;
                float4 a = *(const float4*)(b1e + d);
#pragma unroll
                for (int i = 0; i < 9; ++i) {
                    float4 w = *(const float4*)(w1 + i * 256 + d);
                    a.x += x[i]*w.x; a.y += x[i]*w.y;
                    a.z += x[i]*w.z; a.w += x[i]*w.w;
                }
                a.x = fmaxf(a.x, 0.f); a.y = fmaxf(a.y, 0.f);
                a.z = fmaxf(a.z, 0.f); a.w = fmaxf(a.w, 0.f);
                float hx = __bfloat162float(__float2bfloat16(a.x));
                float hy = __bfloat162float(__float2bfloat16(a.y));
                float hz = __bfloat162float(__float2bfloat16(a.z));
                float hw = __bfloat162float(__float2bfloat16(a.w));
                unsigned o0 = (mrow + gq * 8) ^ amask;
                unsigned o1 = (mrow + gq * 8 + 4) ^ amask;
                *(unsigned*)(smc + OFF_AHI + o0) = pack_bf16x2(a.x, a.y);
                *(unsigned*)(smc + OFF_AHI + o1) = pack_bf16x2(a.z, a.w);
                *(unsigned*)(smc + OFF_ALO + o0) = pack_bf16x2(a.x - hx, a.y - hy);
                *(unsigned*)(smc + OFF_ALO + o1) = pack_bf16x2(a.z - hz, a.w - hw);
            }
        }
        __syncthreads();   // A planes ready (extraction sync fenced prev part)

        float acc[2][8][4];
#pragma unroll
        for (int mt = 0; mt < 2; ++mt)
#pragma unroll
            for (int nt = 0; nt < 8; ++nt)
#pragma unroll
                for (int q = 0; q < 4; ++q) acc[mt][nt][q] = 0.f;
        float acc3[2][4];
#pragma unroll
        for (int t = 0; t < 2; ++t)
#pragma unroll
            for (int q = 0; q < 4; ++q) acc3[t][q] = 0.f;

#pragma unroll 1
        for (int s = 0; s < SPP; ++s) {
            const int g = p * SPP + s;
            // depth-1 prefetch into 3-slot ring. Writes slot (g+1)%3; current
            // readers use g%3, laggards at worst (g-1)%3 -> race-free.
            if (g + 1 < NSTG) {
                prefetch_stage(ring, tid, g + 1);
                asm volatile("cp.async.wait_group 1;" ::: "memory");
            } else {
                asm volatile("cp.async.wait_group 0;" ::: "memory");
            }
            __syncthreads();   // stage g visible; all warps done with stage g-1

            // -------- epilogue between layer2 and layer3 stages --------
            if (s == 16) {
                // all warps finished stage-15 MMAs (sync above), so the h1
                // planes are dead: overwrite with h2 bf16 hi/lo.
#pragma unroll
                for (int mt = 0; mt < 2; ++mt) {
                    const int row0 = wy * 32 + mt * 16 + (lane >> 2);
#pragma unroll
                    for (int nt = 0; nt < 8; ++nt) {
                        const int e = wx * 64 + nt * 8 + (lane & 3) * 2;
                        float2 bv = *(const float2*)(b2g + p * 256 + e);
                        float v0 = fmaxf(acc[mt][nt][0] + bv.x, 0.f);
                        float v1 = fmaxf(acc[mt][nt][1] + bv.y, 0.f);
                        float v2 = fmaxf(acc[mt][nt][2] + bv.x, 0.f);
                        float v3 = fmaxf(acc[mt][nt][3] + bv.y, 0.f);
                        float h0 = __bfloat162float(__float2bfloat16(v0));
                        float h1 = __bfloat162float(__float2bfloat16(v1));
                        float h2 = __bfloat162float(__float2bfloat16(v2));
                        float h3 = __bfloat162float(__float2bfloat16(v3));
                        unsigned o0 = (unsigned)(row0 * 512 + e * 2) ^
                                      (unsigned)((row0 & 7) << 4);
                        unsigned o1 = (unsigned)((row0 + 8) * 512 + e * 2) ^
                                      (unsigned)(((row0 + 8) & 7) << 4);
                        *(unsigned*)(smc + OFF_AHI + o0) = pack_bf16x2(v0, v1);
                        *(unsigned*)(smc + OFF_ALO + o0) = pack_bf16x2(v0 - h0, v1 - h1);
                        *(unsigned*)(smc + OFF_AHI + o1) = pack_bf16x2(v2, v3);
                        *(unsigned*)(smc + OFF_ALO + o1) = pack_bf16x2(v2 - h2, v3 - h3);
                    }
                }
                __syncthreads();   // h2 planes visible to all warps
            }

            const unsigned slot = ring + (unsigned)((g % 3) * 16384);

            if (s < 16) {
                // ---------------- layer2 stage: k-window s>>1 ----------
                const unsigned cw = (unsigned)((s >> 1) * 64);
                if ((s & 1) == 0) {
#pragma unroll
                    for (int ks2 = 0; ks2 < 2; ++ks2) {
                        const unsigned cc = cw + ks2 * 32;
                        unsigned ah[2][4], al[2][4], bb[4][4];
                        LDSM4(ah[0], sb + OFF_AHI + ((a_rb[0] + cc) ^ a_msk[0]));
                        LDSM4(ah[1], sb + OFF_AHI + ((a_rb[1] + cc) ^ a_msk[1]));
                        LDSM4(al[0], sb + OFF_ALO + ((a_rb[0] + cc) ^ a_msk[0]));
                        LDSM4(al[1], sb + OFF_ALO + ((a_rb[1] + cc) ^ a_msk[1]));
#pragma unroll
                        for (int t = 0; t < 4; ++t)
                            LDSM4(bb[t], slot + ((b_off[t] + ks2 * 32) ^ b_sw[t]));
#pragma unroll
                        for (int mt = 0; mt < 2; ++mt)
#pragma unroll
                            for (int t = 0; t < 4; ++t) {
                                MMA16816(acc[mt][2*t],   ah[mt], bb[t][0], bb[t][1]);
                                MMA16816(acc[mt][2*t+1], ah[mt], bb[t][2], bb[t][3]);
                                MMA16816(acc[mt][2*t],   al[mt], bb[t][0], bb[t][1]);
                                MMA16816(acc[mt][2*t+1], al[mt], bb[t][2], bb[t][3]);
                            }
                    }
                } else {
#pragma unroll
                    for (int ks2 = 0; ks2 < 2; ++ks2) {
                        const unsigned cc = cw + ks2 * 32;
                        unsigned ah[2][4], bb[4][4];
                        LDSM4(ah[0], sb + OFF_AHI + ((a_rb[0] + cc) ^ a_msk[0]));
                        LDSM4(ah[1], sb + OFF_AHI + ((a_rb[1] + cc) ^ a_msk[1]));
#pragma unroll
                        for (int t = 0; t < 4; ++t)
                            LDSM4(bb[t], slot + ((b_off[t] + ks2 * 32) ^ b_sw[t]));
#pragma unroll
                        for (int mt = 0; mt < 2; ++mt)
#pragma unroll
                            for (int t = 0; t < 4; ++t) {
                                MMA16816(acc[mt][2*t],   ah[mt], bb[t][0], bb[t][1]);
                                MMA16816(acc[mt][2*t+1], ah[mt], bb[t][2], bb[t][3]);
                            }
                    }
                }
            } else {
                // ---------------- layer3 stage (16=W3hi, 17=W3lo) ------
                const bool hi3 = (s == 16);
#pragma unroll
                for (int ks = 0; ks < 16; ++ks) {
                    const unsigned cc = (unsigned)(ks * 32);
                    unsigned ah[4], al[4], bb[4];
                    LDSM4(ah, sb + OFF_AHI + ((a3_rb + cc) ^ a3_msk));
                    if (hi3) LDSM4(al, sb + OFF_ALO + ((a3_rb + cc) ^ a3_msk));
                    LDSM4(bb, slot + (unsigned)((ks >> 1) * 2048) +
                              ((b3_off + (ks & 1) * 32) ^ b3_sw));
                    MMA16816(acc3[0], ah, bb[0], bb[1]);
                    MMA16816(acc3[1], ah, bb[2], bb[3]);
                    if (hi3) {
                        MMA16816(acc3[0], al, bb[0], bb[1]);
                        MMA16816(acc3[1], al, bb[2], bb[3]);
                    }
                }
            }
            // no trailing sync: 3-slot ring makes next prefetch race-free
        }

        // ---------------- extraction: mask, sigmoid, accumulate --------
        {
            const float fl0 = (tflag[(n0 + r0) * PPARTS + p] != 0) ? 1.f : 0.f;
            const float fl1 = (tflag[(n0 + r1) * PPARTS + p] != 0) ? 1.f : 0.f;
#pragma unroll
            for (int t = 0; t < 2; ++t) {
                const int c = cbase + t * 8;
                const float b3a = g_b3[p * 32 + c];
                const float b3b = g_b3[p * 32 + c + 1];
                float v0 = acc3[t][0] + b3a, v1 = acc3[t][1] + b3b;
                float v2 = acc3[t][2] + b3a, v3 = acc3[t][3] + b3b;
                if (c == 20) {
                    v0 = (1.f / (1.f + __expf(-v0))) * fl0;
                    v2 = (1.f / (1.f + __expf(-v2))) * fl1;
                    out[(size_t)(n0 + r0) * OUTC + 21 + p] = v0;   // tocc
                    out[(size_t)(n0 + r1) * OUTC + 21 + p] = v2;
                } else {
                    v0 *= fl0; v2 *= fl1;
                }
                v1 *= fl0; v3 *= fl1;
                sums[t][0] += v0; sums[t][1] += v1;
                sums[t][2] += v2; sums[t][3] += v3;
            }
        }
        __syncthreads();   // all warps past stage-17 MMAs before next layer1
    }

    // ---------------- final masked means ----------------
    const float inv6 = 1.f / 6.f;
#pragma unroll
    for (int t = 0; t < 2; ++t) {
        const int c = cbase + t * 8;
        if (c < 21) {
            out[(size_t)(n0 + r0) * OUTC + c] = sums[t][0] * inv6;
            out[(size_t)(n0 + r1) * OUTC + c] = sums[t][2] * inv6;
        }
        if (c + 1 < 21) {
            out[(size_t)(n0 + r0) * OUTC + c + 1] = sums[t][1] * inv6;
            out[(size_t)(n0 + r1) * OUTC + c + 1] = sums[t][3] * inv6;
        }
    }
}

// ---------------------------------------------------------------------------
// launch
// ---------------------------------------------------------------------------
extern "C" void kernel_launch(void* const* d_in, const int* in_sizes, int n_in,
                              void* d_out, int out_size) {
    const float* tpts    = (const float*)d_in[0];
    const float* bigpts  = (const float*)d_in[1];
    const float* viewdir = (const float*)d_in[2];
    // d_in[3]=dists, d_in[4]=part_dist unused
    const float* frame   = (const float*)d_in[5];
    const float* W1      = (const float*)d_in[6];
    const float* b1      = (const float*)d_in[7];
    const float* W2      = (const float*)d_in[8];
    const float* b2      = (const float*)d_in[9];
    const float* W3      = (const float*)d_in[10];
    const float* b3      = (const float*)d_in[11];
    const float* Wocc    = (const float*)d_in[12];
    const float* bocc    = (const float*)d_in[13];
    const int*   tflag   = (const int*)d_in[14];
    float* out = (float*)d_out;

    prep_small<<<PPARTS, 256>>>(W1, b1, b3, bocc, frame);
    prep_B2<<<dim3(PPARTS, 256), 256>>>(W2);
    prep_B3<<<dim3(PPARTS, 256), 32>>>(W3, Wocc);

    cudaFuncSetAttribute(fused_kernel,
                         cudaFuncAttributeMaxDynamicSharedMemorySize,
                         SMEM_BYTES);
    fused_kernel<<<NCTAS, THREADS, SMEM_BYTES>>>(tpts, bigpts, viewdir,
                                                 b2, tflag, out);
}